// round 5
// baseline (speedup 1.0000x reference)
#include <cuda_runtime.h>
#include <cuda_fp16.h>

// ---------------- scratch (static, no allocations) ----------------
#define MAXN 1000000
#define MAXE 12000000
#define MAXG 1000
#define HS 8   // halves per row (16B) for h and agg

__device__ __half g_h[MAXN * HS];     // hidden state, fp16 padded rows (16B)
__device__ __half g_agg[MAXN * HS];   // aggregation buffer, fp16 (16B rows)
__device__ __half g_ea16[MAXE * 6];   // fp16 edge_attr cache (written by layer 1)
__device__ float  g_pool[MAXG * 6];
__device__ float  g_cnt[MAXG];

// one 16B fp16 vector reduction: 8 halves (sm_90+)
__device__ __forceinline__ void red8h(__half* p, unsigned r0, unsigned r1,
                                      unsigned r2, unsigned r3) {
    asm volatile("red.global.add.noftz.v4.f16x2 [%0], {%1, %2, %3, %4};"
                 :: "l"(p), "r"(r0), "r"(r1), "r"(r2), "r"(r3) : "memory");
}

__device__ __forceinline__ unsigned pack2(float a, float b) {
    __half2 h = __floats2half2_rn(a, b);
    return *reinterpret_cast<unsigned*>(&h);
}
__device__ __forceinline__ float2 unpack2(unsigned u) {
    return __half22float2(*reinterpret_cast<__half2*>(&u));
}

// message for one edge given gathered h (uint4) and 6 fp32 attrs -> red
__device__ __forceinline__ void emit_msg(__half* o, uint4 hv,
                                         float e0, float e1, float e2,
                                         float e3, float e4, float e5) {
    float2 f0 = unpack2(hv.x), f1 = unpack2(hv.y), f2 = unpack2(hv.z);
    unsigned m0 = pack2(fmaxf(f0.x + e0, 0.f), fmaxf(f0.y + e1, 0.f));
    unsigned m1 = pack2(fmaxf(f1.x + e2, 0.f), fmaxf(f1.y + e3, 0.f));
    unsigned m2 = pack2(fmaxf(f2.x + e4, 0.f), fmaxf(f2.y + e5, 0.f));
    red8h(o, m0, m1, m2, 0u);
}

// ---------------- kernels ----------------

// copy x -> fp16 g_h, zero g_agg / g_pool / g_cnt
__global__ __launch_bounds__(256)
void prep_kernel(const float* __restrict__ x, int N) {
    int n = blockIdx.x * blockDim.x + threadIdx.x;
    if (n < MAXG * 6) g_pool[n] = 0.f;
    if (n < MAXG) g_cnt[n] = 0.f;
    if (n >= N) return;
    const float2* xp = (const float2*)(x + 6ll * n);
    float2 x0 = __ldcs(xp), x1 = __ldcs(xp + 1), x2 = __ldcs(xp + 2);
    uint4 hv;
    hv.x = pack2(x0.x, x0.y);
    hv.y = pack2(x1.x, x1.y);
    hv.z = pack2(x2.x, x2.y);
    hv.w = 0u;
    *(uint4*)(g_h + (long long)HS * n) = hv;
    *(uint4*)(g_agg + (long long)HS * n) = make_uint4(0u, 0u, 0u, 0u);
}

// layer-1 edge kernel: reads fp32 ea, emits messages AND writes fp16 ea cache.
// 4 edges per thread.
__global__ __launch_bounds__(256)
void edge1_kernel(const __half* __restrict__ h,
                  const int* __restrict__ src,
                  const int* __restrict__ dst,
                  const float* __restrict__ ea,
                  __half* __restrict__ agg,
                  __half* __restrict__ ea16, int E)
{
    int t = blockIdx.x * blockDim.x + threadIdx.x;
    int e0 = 4 * t;
    if (e0 >= E) return;

    if (e0 + 3 < E) {
        int4 s4 = __ldcs((const int4*)(src + e0));
        int4 d4 = __ldcs((const int4*)(dst + e0));
        const float4* ap = (const float4*)(ea + 24ll * t);  // 96B for 4 edges
        float4 a0 = __ldcs(ap + 0), a1 = __ldcs(ap + 1), a2 = __ldcs(ap + 2);
        float4 a3 = __ldcs(ap + 3), a4 = __ldcs(ap + 4), a5 = __ldcs(ap + 5);

        uint4 hv0 = __ldg((const uint4*)(h + (long long)HS * s4.x));
        uint4 hv1 = __ldg((const uint4*)(h + (long long)HS * s4.y));
        uint4 hv2 = __ldg((const uint4*)(h + (long long)HS * s4.z));
        uint4 hv3 = __ldg((const uint4*)(h + (long long)HS * s4.w));

        // fp16 ea cache: 24 halves = 3 uint4
        uint4 c0, c1, c2;
        c0.x = pack2(a0.x, a0.y); c0.y = pack2(a0.z, a0.w);
        c0.z = pack2(a1.x, a1.y); c0.w = pack2(a1.z, a1.w);
        c1.x = pack2(a2.x, a2.y); c1.y = pack2(a2.z, a2.w);
        c1.z = pack2(a3.x, a3.y); c1.w = pack2(a3.z, a3.w);
        c2.x = pack2(a4.x, a4.y); c2.y = pack2(a4.z, a4.w);
        c2.z = pack2(a5.x, a5.y); c2.w = pack2(a5.z, a5.w);
        uint4* cp = (uint4*)(ea16 + 24ll * t);
        __stcs(cp + 0, c0); __stcs(cp + 1, c1); __stcs(cp + 2, c2);

        emit_msg(agg + (long long)HS * d4.x, hv0, a0.x, a0.y, a0.z, a0.w, a1.x, a1.y);
        emit_msg(agg + (long long)HS * d4.y, hv1, a1.z, a1.w, a2.x, a2.y, a2.z, a2.w);
        emit_msg(agg + (long long)HS * d4.z, hv2, a3.x, a3.y, a3.z, a3.w, a4.x, a4.y);
        emit_msg(agg + (long long)HS * d4.w, hv3, a4.z, a4.w, a5.x, a5.y, a5.z, a5.w);
    } else {
        for (int e = e0; e < E; e++) {
            int s = __ldcs(src + e), d = __ldcs(dst + e);
            const float2* aep = (const float2*)(ea + 6ll * e);
            float2 b0 = __ldcs(aep), b1 = __ldcs(aep + 1), b2 = __ldcs(aep + 2);
            uint4 hv = __ldg((const uint4*)(h + (long long)HS * s));
            unsigned* cw = (unsigned*)(ea16 + 6ll * e);
            __stcs(cw + 0, pack2(b0.x, b0.y));
            __stcs(cw + 1, pack2(b1.x, b1.y));
            __stcs(cw + 2, pack2(b2.x, b2.y));
            emit_msg(agg + (long long)HS * d, hv, b0.x, b0.y, b1.x, b1.y, b2.x, b2.y);
        }
    }
}

// layers 2/3 edge kernel: reads fp16 ea cache. 4 edges per thread.
__global__ __launch_bounds__(256)
void edge2_kernel(const __half* __restrict__ h,
                  const int* __restrict__ src,
                  const int* __restrict__ dst,
                  const __half* __restrict__ ea16,
                  __half* __restrict__ agg, int E)
{
    int t = blockIdx.x * blockDim.x + threadIdx.x;
    int e0 = 4 * t;
    if (e0 >= E) return;

    if (e0 + 3 < E) {
        int4 s4 = __ldcs((const int4*)(src + e0));
        int4 d4 = __ldcs((const int4*)(dst + e0));
        const uint4* cp = (const uint4*)(ea16 + 24ll * t);  // 48B for 4 edges
        uint4 c0 = __ldcs(cp + 0), c1 = __ldcs(cp + 1), c2 = __ldcs(cp + 2);

        uint4 hv0 = __ldg((const uint4*)(h + (long long)HS * s4.x));
        uint4 hv1 = __ldg((const uint4*)(h + (long long)HS * s4.y));
        uint4 hv2 = __ldg((const uint4*)(h + (long long)HS * s4.z));
        uint4 hv3 = __ldg((const uint4*)(h + (long long)HS * s4.w));

        float2 e0a = unpack2(c0.x), e0b = unpack2(c0.y), e0c = unpack2(c0.z);
        float2 e1a = unpack2(c0.w), e1b = unpack2(c1.x), e1c = unpack2(c1.y);
        float2 e2a = unpack2(c1.z), e2b = unpack2(c1.w), e2c = unpack2(c2.x);
        float2 e3a = unpack2(c2.y), e3b = unpack2(c2.z), e3c = unpack2(c2.w);

        emit_msg(agg + (long long)HS * d4.x, hv0, e0a.x, e0a.y, e0b.x, e0b.y, e0c.x, e0c.y);
        emit_msg(agg + (long long)HS * d4.y, hv1, e1a.x, e1a.y, e1b.x, e1b.y, e1c.x, e1c.y);
        emit_msg(agg + (long long)HS * d4.z, hv2, e2a.x, e2a.y, e2b.x, e2b.y, e2c.x, e2c.y);
        emit_msg(agg + (long long)HS * d4.w, hv3, e3a.x, e3a.y, e3b.x, e3b.y, e3c.x, e3c.y);
    } else {
        for (int e = e0; e < E; e++) {
            int s = __ldcs(src + e), d = __ldcs(dst + e);
            const unsigned* cw = (const unsigned*)(ea16 + 6ll * e);
            float2 b0 = unpack2(__ldcs(cw + 0));
            float2 b1 = unpack2(__ldcs(cw + 1));
            float2 b2 = unpack2(__ldcs(cw + 2));
            uint4 hv = __ldg((const uint4*)(h + (long long)HS * s));
            emit_msg(agg + (long long)HS * d, hv, b0.x, b0.y, b1.x, b1.y, b2.x, b2.y);
        }
    }
}

// update: hout = relu((hin + agg) @ W + b); zero agg for next layer
__global__ __launch_bounds__(256)
void node_kernel(const __half* __restrict__ hin,
                 __half* __restrict__ agg,
                 const float* __restrict__ W,
                 const float* __restrict__ b,
                 __half* __restrict__ hout, int N)
{
    int n = blockIdx.x * blockDim.x + threadIdx.x;
    if (n >= N) return;
    uint4 hv = *(const uint4*)(hin + (long long)HS * n);
    uint4* gp = (uint4*)(agg + (long long)HS * n);
    uint4 gv = *gp;
    *gp = make_uint4(0u, 0u, 0u, 0u);

    float2 h0 = unpack2(hv.x), h1 = unpack2(hv.y), h2 = unpack2(hv.z);
    float2 q0 = unpack2(gv.x), q1 = unpack2(gv.y), q2 = unpack2(gv.z);
    float t[6] = { h0.x + q0.x, h0.y + q0.y, h1.x + q1.x,
                   h1.y + q1.y, h2.x + q2.x, h2.y + q2.y };

    float o[6];
    #pragma unroll
    for (int j = 0; j < 6; j++) {
        float acc = __ldg(b + j);
        #pragma unroll
        for (int i = 0; i < 6; i++) acc += t[i] * __ldg(W + i * 6 + j);
        o[j] = fmaxf(acc, 0.f);
    }
    uint4 ov;
    ov.x = pack2(o[0], o[1]);
    ov.y = pack2(o[2], o[3]);
    ov.z = pack2(o[4], o[5]);
    ov.w = 0u;
    *(uint4*)(hout + (long long)HS * n) = ov;
}

// layer-3 update fused with mean-pool accumulation (batch is sorted).
__global__ __launch_bounds__(256)
void node3_pool_kernel(const __half* __restrict__ hin,
                       const __half* __restrict__ agg,
                       const float* __restrict__ W,
                       const float* __restrict__ b,
                       const int* __restrict__ batch, int N)
{
    int n = blockIdx.x * blockDim.x + threadIdx.x;
    bool valid = (n < N);
    int nn = valid ? n : (N - 1);

    uint4 hv = *(const uint4*)(hin + (long long)HS * nn);
    uint4 gv = *(const uint4*)(agg + (long long)HS * nn);

    float2 h0 = unpack2(hv.x), h1 = unpack2(hv.y), h2 = unpack2(hv.z);
    float2 q0 = unpack2(gv.x), q1 = unpack2(gv.y), q2 = unpack2(gv.z);
    float t[6] = { h0.x + q0.x, h0.y + q0.y, h1.x + q1.x,
                   h1.y + q1.y, h2.x + q2.x, h2.y + q2.y };

    float o[6];
    #pragma unroll
    for (int j = 0; j < 6; j++) {
        float acc = __ldg(b + j);
        #pragma unroll
        for (int i = 0; i < 6; i++) acc += t[i] * __ldg(W + i * 6 + j);
        o[j] = valid ? acc : 0.f;
    }
    float c = valid ? 1.f : 0.f;
    int g = __ldg(batch + nn);

    unsigned lane = threadIdx.x & 31u;
    unsigned peers = __match_any_sync(0xffffffffu, g);  // contiguous (sorted)
    int leader = __ffs(peers) - 1;

    #pragma unroll
    for (int j = 0; j < 6; j++) {
        float v = o[j];
        #pragma unroll
        for (int off = 1; off < 32; off <<= 1) {
            float tv = __shfl_down_sync(0xffffffffu, v, off);
            if (lane + off < 32 && ((peers >> (lane + off)) & 1u)) v += tv;
        }
        if ((int)lane == leader) atomicAdd(&g_pool[g * 6 + j], v);
    }
    {
        float v = c;
        #pragma unroll
        for (int off = 1; off < 32; off <<= 1) {
            float tv = __shfl_down_sync(0xffffffffu, v, off);
            if (lane + off < 32 && ((peers >> (lane + off)) & 1u)) v += tv;
        }
        if ((int)lane == leader) atomicAdd(&g_cnt[g], v);
    }
}

__global__ void final_kernel(const float* __restrict__ Wl,
                             const float* __restrict__ bl,
                             float* __restrict__ out, int G)
{
    int g = blockIdx.x * blockDim.x + threadIdx.x;
    if (g >= G) return;
    float c = fmaxf(g_cnt[g], 1.f);
    float s = 0.f;
    #pragma unroll
    for (int i = 0; i < 6; i++) s += (g_pool[g * 6 + i] / c) * __ldg(Wl + i);
    out[g] = s + __ldg(bl);
}

// ---------------- launch ----------------

extern "C" void kernel_launch(void* const* d_in, const int* in_sizes, int n_in,
                              void* d_out, int out_size)
{
    const float* x     = (const float*)d_in[0];
    const int*   ei    = (const int*)d_in[1];     // int32 (JAX demotes int64)
    const float* ea    = (const float*)d_in[2];
    const int*   batch = (const int*)d_in[3];
    const float* W1 = (const float*)d_in[4];
    const float* b1 = (const float*)d_in[5];
    const float* W2 = (const float*)d_in[6];
    const float* b2 = (const float*)d_in[7];
    const float* W3 = (const float*)d_in[8];
    const float* b3 = (const float*)d_in[9];
    const float* Wl = (const float*)d_in[10];
    const float* bl = (const float*)d_in[11];
    float* out = (float*)d_out;

    int N = in_sizes[0] / 6;
    int E = in_sizes[1] / 2;
    int G = out_size;

    const int* src = ei;
    const int* dst = ei + E;

    __half* h;    cudaGetSymbolAddress((void**)&h,    g_h);
    __half* agg;  cudaGetSymbolAddress((void**)&agg,  g_agg);
    __half* ea16; cudaGetSymbolAddress((void**)&ea16, g_ea16);

    int nb_node = (N + 255) / 256;
    int nb_edge4 = ((E + 3) / 4 + 255) / 256;

    prep_kernel<<<nb_node, 256>>>(x, N);

    // layer 1 (fp32 ea; also builds fp16 ea cache)
    edge1_kernel<<<nb_edge4, 256>>>(h, src, dst, ea, agg, ea16, E);
    node_kernel<<<nb_node, 256>>>(h, agg, W1, b1, h, N);

    // layer 2 (fp16 ea)
    edge2_kernel<<<nb_edge4, 256>>>(h, src, dst, ea16, agg, E);
    node_kernel<<<nb_node, 256>>>(h, agg, W2, b2, h, N);

    // layer 3 + pooling (fused)
    edge2_kernel<<<nb_edge4, 256>>>(h, src, dst, ea16, agg, E);
    node3_pool_kernel<<<nb_node, 256>>>(h, agg, W3, b3, batch, N);

    final_kernel<<<(G + 127) / 128, 128>>>(Wl, bl, out, G);
}